// round 12
// baseline (speedup 1.0000x reference)
#include <cuda_runtime.h>
#include <math.h>
#include <stdint.h>

// ---------------- problem constants ----------------
#define N_NODES 50000
#define N_REL   50
#define N_BASES 30
#define NSEG    (N_NODES * N_REL)
#define MAXE    1100000
#define SCAN_CHUNK 2048
#define NB2 ((NSEG + SCAN_CHUNK - 1) / SCAN_CHUNK)
#define FULLM 0xffffffffu

// ---------------- static device scratch (zero-initialized at load) ----------------
__device__ int d_cnt[NSEG];
__device__ int d_off[NSEG + 1];
__device__ int d_cpt[NSEG + 1];
__device__ int d_cur[NSEG];
__device__ int d_coff[MAXE + 2];
__device__ int d_cdst[MAXE];
__device__ int d_srcn[MAXE];
__device__ unsigned long long d_agg[NB2];
__device__ unsigned long long d_incl[NB2];
__device__ int d_stat[NB2];
__device__ int d_bidc;
__device__ float d_W0[N_REL * 64 * 64];   // fragment-order (see k_prep)
__device__ float d_W1[N_REL * 64 * 64];   // fragment-order
__device__ float d_W2[N_REL * 64 * 8];    // k-major (SIMT path)
__device__ float d_msg[N_NODES * 64];
__device__ float d_hA[N_NODES * 64];
__device__ float d_hB[N_NODES * 64];

__device__ __forceinline__ float tf32r(float v) {
    uint32_t u;
    asm("cvt.rna.tf32.f32 %0, %1;" : "=r"(u) : "f"(v));
    return __uint_as_float(u);
}
__device__ __forceinline__ void red2(float* p, float a, float b) {
    asm volatile("red.global.add.v2.f32 [%0], {%1, %2};" :: "l"(p), "f"(a), "f"(b) : "memory");
}
__device__ __forceinline__ void red4(float* p, float a, float b, float c, float d) {
    asm volatile("red.global.add.v4.f32 [%0], {%1, %2, %3, %4};"
                 :: "l"(p), "f"(a), "f"(b), "f"(c), "f"(d) : "memory");
}

// ---------------- fused prep: edge histogram + W precomputes ----------------
// W0/W1 in MMA B-fragment order:
//   fi in [0,4096): s=fi&3, lane=(fi>>2)&31, jp=(fi>>7)&3, kk=fi>>9
//   j = 2*jp + (s>>1), hb = s&1, q = lane&3, g = lane>>2
//   k = kk*8 + q + hb*4,  o = j*8 + g  ->  W[r][k][o]
__global__ void k_prep(const int* __restrict__ et, const int* __restrict__ dst, int E,
                       const float* __restrict__ b0, const float* __restrict__ c0,
                       const float* __restrict__ b1, const float* __restrict__ c1,
                       const float* __restrict__ b2, const float* __restrict__ c2) {
    int i = blockIdx.x * blockDim.x + threadIdx.x;
    if (i < E) atomicAdd(&d_cnt[et[i] * N_NODES + dst[i]], 1);
    if (i < N_REL * 64 * 64) {
        int r = i >> 12, fi = i & 4095;
        int s = fi & 3, lane = (fi >> 2) & 31, jp = (fi >> 7) & 3, kk = fi >> 9;
        int j = 2 * jp + (s >> 1);
        int hb = s & 1;
        int q = lane & 3, g = lane >> 2;
        int k = kk * 8 + q + hb * 4;
        int o = j * 8 + g;
        int ko = k * 64 + o;
        float a0 = 0.f, a1 = 0.f;
#pragma unroll 6
        for (int b = 0; b < N_BASES; b++) {
            a0 += c0[r * N_BASES + b] * b0[b * 4096 + ko];
            a1 += c1[r * N_BASES + b] * b1[b * 4096 + ko];
        }
        d_W0[i] = tf32r(a0);
        d_W1[i] = tf32r(a1);
    }
    if (i < N_REL * 64 * 8) {
        int r = i >> 9, ko = i & 511;
        float a2 = 0.f;
#pragma unroll 6
        for (int b = 0; b < N_BASES; b++)
            a2 += c2[r * N_BASES + b] * b2[b * 512 + ko];
        d_W2[i] = a2;
    }
}

// single-pass decoupled-lookback scan of (cnt, cnt>0)
__global__ void __launch_bounds__(256) k_scan() {
    __shared__ int sbid;
    __shared__ unsigned long long sexcl;
    __shared__ int ssum[256], sflg[256];
    int t = threadIdx.x;
    if (t == 0) sbid = atomicAdd(&d_bidc, 1);
    __syncthreads();
    int bid = sbid;
    int base = bid * SCAN_CHUNK + t * 8;
    int v[8], f[8];
    int run1 = 0, run2 = 0;
#pragma unroll
    for (int j = 0; j < 8; j++) {
        int idx = base + j;
        int c = (idx < NSEG) ? d_cnt[idx] : 0;
        v[j] = run1; f[j] = run2;
        run1 += c; run2 += (c > 0);
    }
    ssum[t] = run1; sflg[t] = run2;
    __syncthreads();
    for (int d = 1; d < 256; d <<= 1) {
        int a = 0, b = 0;
        if (t >= d) { a = ssum[t - d]; b = sflg[t - d]; }
        __syncthreads();
        if (t >= d) { ssum[t] += a; sflg[t] += b; }
        __syncthreads();
    }
    unsigned long long blockAgg =
        ((unsigned long long)(unsigned)ssum[255] << 32) | (unsigned)sflg[255];
    if (t == 0) {
        *((volatile unsigned long long*)&d_agg[bid]) = blockAgg;
        __threadfence();
        *((volatile int*)&d_stat[bid]) = 1;
    }
    if (t < 32) {
        unsigned long long excl = 0;
        int p = bid - 1;
        while (p >= 0) {
            int pi = p - t;
            int st;
            do {
                st = (pi >= 0) ? *((volatile int*)&d_stat[pi]) : 2;
            } while (__any_sync(FULLM, st == 0));
            unsigned m2 = __ballot_sync(FULLM, pi >= 0 && st == 2);
            if (m2) {
                int lead = __ffs(m2) - 1;
                unsigned long long vv = 0ull;
                if (pi >= 0) {
                    if (t < lead)       vv = *((volatile unsigned long long*)&d_agg[pi]);
                    else if (t == lead) vv = *((volatile unsigned long long*)&d_incl[pi]);
                }
                for (int o = 16; o > 0; o >>= 1) vv += __shfl_down_sync(FULLM, vv, o);
                excl += __shfl_sync(FULLM, vv, 0);
                break;
            } else {
                unsigned long long vv =
                    (pi >= 0) ? *((volatile unsigned long long*)&d_agg[pi]) : 0ull;
                for (int o = 16; o > 0; o >>= 1) vv += __shfl_down_sync(FULLM, vv, o);
                excl += __shfl_sync(FULLM, vv, 0);
                p -= 32;
            }
        }
        if (t == 0) {
            sexcl = excl;
            *((volatile unsigned long long*)&d_incl[bid]) = excl + blockAgg;
            __threadfence();
            *((volatile int*)&d_stat[bid]) = 2;
        }
    }
    __syncthreads();
    int exS = (int)(sexcl >> 32), exF = (int)(sexcl & 0xffffffffu);
    int ts = exS + ssum[t] - run1;
    int tf = exF + sflg[t] - run2;
#pragma unroll
    for (int j = 0; j < 8; j++) {
        int idx = base + j;
        if (idx < NSEG) {
            int o = ts + v[j];
            d_off[idx] = o; d_cur[idx] = o; d_cpt[idx] = tf + f[j];
        }
    }
    if (bid == NB2 - 1 && t == 255) {
        d_off[NSEG] = exS + ssum[255];
        d_cpt[NSEG] = exF + sflg[255];
    }
}

// compact CSR + counting-sort scatter + state reset for next replay
__global__ void k_cscat(const int* __restrict__ et, const int* __restrict__ dst,
                        const int* __restrict__ src, int E) {
    int i = blockIdx.x * blockDim.x + threadIdx.x;
    if (i < NSEG) {
        int c = d_cnt[i];
        if (c > 0) {
            int cc = d_cpt[i];
            d_coff[cc] = d_off[i];
            d_cdst[cc] = i % N_NODES;
        }
        d_cnt[i] = 0;
    }
    if (i < E) {
        int key = et[i] * N_NODES + dst[i];
        int p = atomicAdd(&d_cur[key], 1);
        d_srcn[p] = src[i];
    }
    if (i < NB2) d_stat[i] = 0;
    if (i == 0) {
        d_bidc = 0;
        d_coff[d_cpt[NSEG]] = E;
    }
}

// ---------------- fused mean aggregation + tf32 MMA + red scatter ----------------
// Block = 256 compact segments of one relation; warp owns 32 rows (2 MMA tiles).
// B fragments loaded once per (kk,jp) and reused for both tiles -> B L1 traffic
// per segment halved vs the 128-seg version.
template <int DOUT>
__global__ void __launch_bounds__(256) k_agg(const float* __restrict__ x,
                                             const float* __restrict__ W) {
    extern __shared__ float smem[];
    float* Ws;   // only for DOUT==8
    float* As;
    if (DOUT == 8) { Ws = smem; As = smem + 64 * 8; }
    else           { Ws = nullptr; As = smem; }
    int* sso = (int*)(As + 256 * 68);   // [257]
    int* sdn = sso + 257;               // [256]

    int r = blockIdx.y;
    int t = threadIdx.x, lane = t & 31, w = t >> 5;

    int baseC = d_cpt[r * N_NODES];
    int Cend  = d_cpt[(r + 1) * N_NODES];
    int cb    = baseC + blockIdx.x * 256;
    if (cb >= Cend) return;

    if (DOUT == 8) {
        const float* Wr = W + r * 64 * 8;
        for (int i = t; i < 64 * 8; i += 256) Ws[i] = Wr[i];
    }
    // segment metadata
    if (t < 257) sso[t] = d_coff[min(cb + t, Cend)];
    {
        int t2 = t + 256;
        if (t2 == 256) sso[256] = d_coff[min(cb + 256, Cend)];
    }
    if (t < 256) sdn[t] = (cb + t < Cend) ? d_cdst[cb + t] : -1;
    __syncthreads();

    // ---- gather: 8 threads/segment, 2 chunks x 4 unrolled passes ----
    {
        int sub  = t & 7;
        int c0   = sub * 8;
        int segl = t >> 3;
#pragma unroll
        for (int ch = 0; ch < 2; ch++) {
            int sb = ch * 128;
            int e0[4], e1[4], s0[4];
#pragma unroll
            for (int p = 0; p < 4; p++) {
                int sg = sb + p * 32 + segl;
                e0[p] = sso[sg];
                e1[p] = sso[sg + 1];
            }
#pragma unroll
            for (int p = 0; p < 4; p++)
                s0[p] = (e1[p] > e0[p]) ? __ldg(&d_srcn[e0[p]]) : -1;
            float4 A0[4], A1[4];
#pragma unroll
            for (int p = 0; p < 4; p++) {
                if (s0[p] >= 0) {
                    const float4* xp = (const float4*)(x + s0[p] * 64 + c0);
                    A0[p] = __ldg(xp);
                    A1[p] = __ldg(xp + 1);
                } else {
                    A0[p] = make_float4(0.f, 0.f, 0.f, 0.f);
                    A1[p] = make_float4(0.f, 0.f, 0.f, 0.f);
                }
            }
#pragma unroll
            for (int p = 0; p < 4; p++) {
                for (int e = e0[p] + 1; e < e1[p]; e++) {
                    int s2 = __ldg(&d_srcn[e]);
                    const float4* xq = (const float4*)(x + s2 * 64 + c0);
                    float4 v0 = __ldg(xq), v1 = __ldg(xq + 1);
                    A0[p].x += v0.x; A0[p].y += v0.y; A0[p].z += v0.z; A0[p].w += v0.w;
                    A1[p].x += v1.x; A1[p].y += v1.y; A1[p].z += v1.z; A1[p].w += v1.w;
                }
            }
#pragma unroll
            for (int p = 0; p < 4; p++) {
                int cnt = e1[p] - e0[p];
                float inv = (cnt > 0) ? 1.f / (float)cnt : 0.f;
                int sg = sb + p * 32 + segl;
                float* dp = As + sg * 68 + c0;
                float4 o0, o1;
                o0.x = tf32r(A0[p].x * inv); o0.y = tf32r(A0[p].y * inv);
                o0.z = tf32r(A0[p].z * inv); o0.w = tf32r(A0[p].w * inv);
                o1.x = tf32r(A1[p].x * inv); o1.y = tf32r(A1[p].y * inv);
                o1.z = tf32r(A1[p].z * inv); o1.w = tf32r(A1[p].w * inv);
                *(float4*)dp = o0;
                *(float4*)(dp + 4) = o1;
            }
        }
    }
    __syncthreads();

    if (DOUT == 64) {
        int g = lane >> 2, q = lane & 3;
        const float* AL0 = As + (w * 32 + g) * 68;        // tile 0 rows g, g+8
        const float* AL8 = AL0 + 8 * 68;
        const float* AH0 = AL0 + 16 * 68;                 // tile 1 rows g+16, g+24
        const float* AH8 = AL0 + 24 * 68;
        const float4* Wf = (const float4*)(W + r * 4096);
        float mac[2][8][4];
#pragma unroll
        for (int tt = 0; tt < 2; tt++)
#pragma unroll
            for (int j = 0; j < 8; j++)
#pragma unroll
                for (int i = 0; i < 4; i++) mac[tt][j][i] = 0.f;
#pragma unroll
        for (int kk = 0; kk < 8; kk++) {
            int k0 = kk * 8;
            uint32_t L0 = __float_as_uint(AL0[k0 + q]);
            uint32_t L1 = __float_as_uint(AL8[k0 + q]);
            uint32_t L2 = __float_as_uint(AL0[k0 + q + 4]);
            uint32_t L3 = __float_as_uint(AL8[k0 + q + 4]);
            uint32_t H0 = __float_as_uint(AH0[k0 + q]);
            uint32_t H1 = __float_as_uint(AH8[k0 + q]);
            uint32_t H2 = __float_as_uint(AH0[k0 + q + 4]);
            uint32_t H3 = __float_as_uint(AH8[k0 + q + 4]);
#pragma unroll
            for (int jp = 0; jp < 4; jp++) {
                float4 bf = __ldg(&Wf[(kk * 4 + jp) * 32 + lane]);
                uint32_t B0 = __float_as_uint(bf.x);
                uint32_t B1 = __float_as_uint(bf.y);
                uint32_t B2 = __float_as_uint(bf.z);
                uint32_t B3 = __float_as_uint(bf.w);
                asm volatile(
                    "mma.sync.aligned.m16n8k8.row.col.f32.tf32.tf32.f32 "
                    "{%0,%1,%2,%3}, {%4,%5,%6,%7}, {%8,%9}, {%0,%1,%2,%3};"
                    : "+f"(mac[0][2*jp][0]), "+f"(mac[0][2*jp][1]),
                      "+f"(mac[0][2*jp][2]), "+f"(mac[0][2*jp][3])
                    : "r"(L0), "r"(L1), "r"(L2), "r"(L3), "r"(B0), "r"(B1));
                asm volatile(
                    "mma.sync.aligned.m16n8k8.row.col.f32.tf32.tf32.f32 "
                    "{%0,%1,%2,%3}, {%4,%5,%6,%7}, {%8,%9}, {%0,%1,%2,%3};"
                    : "+f"(mac[0][2*jp+1][0]), "+f"(mac[0][2*jp+1][1]),
                      "+f"(mac[0][2*jp+1][2]), "+f"(mac[0][2*jp+1][3])
                    : "r"(L0), "r"(L1), "r"(L2), "r"(L3), "r"(B2), "r"(B3));
                asm volatile(
                    "mma.sync.aligned.m16n8k8.row.col.f32.tf32.tf32.f32 "
                    "{%0,%1,%2,%3}, {%4,%5,%6,%7}, {%8,%9}, {%0,%1,%2,%3};"
                    : "+f"(mac[1][2*jp][0]), "+f"(mac[1][2*jp][1]),
                      "+f"(mac[1][2*jp][2]), "+f"(mac[1][2*jp][3])
                    : "r"(H0), "r"(H1), "r"(H2), "r"(H3), "r"(B0), "r"(B1));
                asm volatile(
                    "mma.sync.aligned.m16n8k8.row.col.f32.tf32.tf32.f32 "
                    "{%0,%1,%2,%3}, {%4,%5,%6,%7}, {%8,%9}, {%0,%1,%2,%3};"
                    : "+f"(mac[1][2*jp+1][0]), "+f"(mac[1][2*jp+1][1]),
                      "+f"(mac[1][2*jp+1][2]), "+f"(mac[1][2*jp+1][3])
                    : "r"(H0), "r"(H1), "r"(H2), "r"(H3), "r"(B2), "r"(B3));
            }
        }
#pragma unroll
        for (int tt = 0; tt < 2; tt++) {
            int dA = sdn[w * 32 + tt * 16 + g];
            int dB = sdn[w * 32 + tt * 16 + 8 + g];
#pragma unroll
            for (int j = 0; j < 8; j++) {
                int col = j * 8 + 2 * q;
                if (dA >= 0) red2(&d_msg[dA * 64 + col], mac[tt][j][0], mac[tt][j][1]);
                if (dB >= 0) red2(&d_msg[dB * 64 + col], mac[tt][j][2], mac[tt][j][3]);
            }
        }
    } else {
        int c0 = (t & 1) * 4;
#pragma unroll
        for (int half = 0; half < 2; half++) {
            int row = (t >> 1) + half * 128;
            const float* Ar = As + row * 68;
            float s0 = 0.f, s1 = 0.f, s2 = 0.f, s3 = 0.f;
#pragma unroll
            for (int k = 0; k < 64; k++) {
                float a = Ar[k];
                float4 b = *(const float4*)&Ws[k * 8 + c0];
                s0 += a * b.x; s1 += a * b.y; s2 += a * b.z; s3 += a * b.w;
            }
            int dn = sdn[row];
            if (dn >= 0) red4(&d_msg[dn * 8 + c0], s0, s1, s2, s3);
        }
    }
}

// epilogue: h = relu(msg + x@root + bias); re-zero msg
__global__ void k_rootrelu(const float* __restrict__ x, const float* __restrict__ root,
                           const float* __restrict__ bias, float* __restrict__ h) {
    int idx = blockIdx.x * blockDim.x + threadIdx.x;
    if (idx >= N_NODES * 64) return;
    int n = idx >> 6, o = idx & 63;
    float acc = bias[o] + d_msg[idx];
    d_msg[idx] = 0.f;
    const float* xr = x + n * 64;
#pragma unroll 16
    for (int i = 0; i < 64; i++) acc += xr[i] * root[i * 64 + o];
    h[idx] = acc > 0.f ? acc : 0.f;
}

// final epilogue: out = log_softmax(msg + x@root + bias); re-zero msg slice
__global__ void k_rootlsm(const float* __restrict__ x, const float* __restrict__ root,
                          const float* __restrict__ bias, float* __restrict__ out) {
    int n = blockIdx.x * blockDim.x + threadIdx.x;
    if (n >= N_NODES) return;
    float v[8];
#pragma unroll
    for (int c = 0; c < 8; c++) {
        v[c] = bias[c] + d_msg[n * 8 + c];
        d_msg[n * 8 + c] = 0.f;
    }
    const float* xr = x + n * 64;
    for (int i = 0; i < 64; i++) {
        float xv = xr[i];
#pragma unroll
        for (int c = 0; c < 8; c++) v[c] += xv * root[i * 8 + c];
    }
    float m = -1e30f;
#pragma unroll
    for (int c = 0; c < 8; c++) m = fmaxf(m, v[c]);
    float s = 0.f;
#pragma unroll
    for (int c = 0; c < 8; c++) s += expf(v[c] - m);
    float ls = logf(s) + m;
#pragma unroll
    for (int c = 0; c < 8; c++) out[n * 8 + c] = v[c] - ls;
}

// ---------------- launch ----------------
extern "C" void kernel_launch(void* const* d_in, const int* in_sizes, int n_in,
                              void* d_out, int out_size) {
    const float* x0 = (const float*)d_in[0];
    const int* ei = (const int*)d_in[1];
    const int* et = (const int*)d_in[2];
    int E = in_sizes[2];
    const int* src = ei;
    const int* dst = ei + E;

    void *pA, *pB, *pW0, *pW1, *pW2;
    cudaGetSymbolAddress(&pA, d_hA);
    cudaGetSymbolAddress(&pB, d_hB);
    cudaGetSymbolAddress(&pW0, d_W0);
    cudaGetSymbolAddress(&pW1, d_W1);
    cudaGetSymbolAddress(&pW2, d_W2);
    float* hA = (float*)pA;
    float* hB = (float*)pB;

    const int SMEM64 = (256 * 68) * 4 + 257 * 4 + 256 * 4;
    const int SMEM8  = (64 * 8 + 256 * 68) * 4 + 257 * 4 + 256 * 4;
    cudaFuncSetAttribute(k_agg<64>, cudaFuncAttributeMaxDynamicSharedMemorySize, SMEM64);
    cudaFuncSetAttribute(k_agg<8>,  cudaFuncAttributeMaxDynamicSharedMemorySize, SMEM8);

    const int NZ = N_NODES * 64;
    dim3 grid((N_NODES + 255) / 256, N_REL);

    // 1: prep;  2: scan;  3: compact+scatter+reset;  4: k_agg<64>  <- ncu slot
    k_prep<<<(E + 255) / 256, 256>>>(et, dst, E,
        (const float*)d_in[3], (const float*)d_in[4],
        (const float*)d_in[7], (const float*)d_in[8],
        (const float*)d_in[11], (const float*)d_in[12]);
    k_scan<<<NB2, 256>>>();
    k_cscat<<<(NSEG + 255) / 256, 256>>>(et, dst, src, E);

    k_agg<64><<<grid, 256, SMEM64>>>(x0, (const float*)pW0);
    k_rootrelu<<<(NZ + 255) / 256, 256>>>(x0, (const float*)d_in[5], (const float*)d_in[6], hA);

    k_agg<64><<<grid, 256, SMEM64>>>(hA, (const float*)pW1);
    k_rootrelu<<<(NZ + 255) / 256, 256>>>(hA, (const float*)d_in[9], (const float*)d_in[10], hB);

    k_agg<8><<<grid, 256, SMEM8>>>(hB, (const float*)pW2);
    k_rootlsm<<<(N_NODES + 255) / 256, 256>>>(hB, (const float*)d_in[13], (const float*)d_in[14],
                                              (float*)d_out);
}

// round 13
// speedup vs baseline: 1.7717x; 1.7717x over previous
#include <cuda_runtime.h>
#include <math.h>
#include <stdint.h>

// ---------------- problem constants ----------------
#define N_NODES 50000
#define N_REL   50
#define N_BASES 30
#define NSEG    (N_NODES * N_REL)
#define MAXE    1100000
#define SCAN_CHUNK 2048
#define NB2 ((NSEG + SCAN_CHUNK - 1) / SCAN_CHUNK)
#define FULLM 0xffffffffu

// ---------------- static device scratch (zero-initialized at load) ----------------
__device__ int d_cnt[NSEG];
__device__ int d_off[NSEG + 1];
__device__ int d_cpt[NSEG + 1];
__device__ int d_cur[NSEG];
__device__ int d_coff[MAXE + 2];
__device__ int d_cdst[MAXE];
__device__ int d_srcn[MAXE];
__device__ unsigned long long d_agg[NB2];
__device__ unsigned long long d_incl[NB2];
__device__ int d_stat[NB2];
__device__ int d_bidc;
__device__ float d_W0[N_REL * 64 * 64];   // fragment-order (see k_prep)
__device__ float d_W1[N_REL * 64 * 64];   // fragment-order
__device__ float d_W2[N_REL * 64 * 8];    // k-major (SIMT path)
__device__ float d_msg[N_NODES * 64];
__device__ float d_hA[N_NODES * 64];
__device__ float d_hB[N_NODES * 64];

__device__ __forceinline__ float tf32r(float v) {
    uint32_t u;
    asm("cvt.rna.tf32.f32 %0, %1;" : "=r"(u) : "f"(v));
    return __uint_as_float(u);
}
__device__ __forceinline__ void red2(float* p, float a, float b) {
    asm volatile("red.global.add.v2.f32 [%0], {%1, %2};" :: "l"(p), "f"(a), "f"(b) : "memory");
}
__device__ __forceinline__ void red4(float* p, float a, float b, float c, float d) {
    asm volatile("red.global.add.v4.f32 [%0], {%1, %2, %3, %4};"
                 :: "l"(p), "f"(a), "f"(b), "f"(c), "f"(d) : "memory");
}

// ---------------- fused prep: edge histogram + W precomputes ----------------
// W0/W1 in MMA B-fragment order:
//   fi in [0,4096): s=fi&3, lane=(fi>>2)&31, jp=(fi>>7)&3, kk=fi>>9
//   j = 2*jp + (s>>1), hb = s&1, q = lane&3, g = lane>>2
//   k = kk*8 + q + hb*4,  o = j*8 + g  ->  W[r][k][o]
__global__ void k_prep(const int* __restrict__ et, const int* __restrict__ dst, int E,
                       const float* __restrict__ b0, const float* __restrict__ c0,
                       const float* __restrict__ b1, const float* __restrict__ c1,
                       const float* __restrict__ b2, const float* __restrict__ c2) {
    int i = blockIdx.x * blockDim.x + threadIdx.x;
    if (i < E) atomicAdd(&d_cnt[et[i] * N_NODES + dst[i]], 1);
    if (i < N_REL * 64 * 64) {
        int r = i >> 12, fi = i & 4095;
        int s = fi & 3, lane = (fi >> 2) & 31, jp = (fi >> 7) & 3, kk = fi >> 9;
        int j = 2 * jp + (s >> 1);
        int hb = s & 1;
        int q = lane & 3, g = lane >> 2;
        int k = kk * 8 + q + hb * 4;
        int o = j * 8 + g;
        int ko = k * 64 + o;
        float a0 = 0.f, a1 = 0.f;
#pragma unroll 6
        for (int b = 0; b < N_BASES; b++) {
            a0 += c0[r * N_BASES + b] * b0[b * 4096 + ko];
            a1 += c1[r * N_BASES + b] * b1[b * 4096 + ko];
        }
        d_W0[i] = tf32r(a0);
        d_W1[i] = tf32r(a1);
    }
    if (i < N_REL * 64 * 8) {
        int r = i >> 9, ko = i & 511;
        float a2 = 0.f;
#pragma unroll 6
        for (int b = 0; b < N_BASES; b++)
            a2 += c2[r * N_BASES + b] * b2[b * 512 + ko];
        d_W2[i] = a2;
    }
}

// single-pass decoupled-lookback scan of (cnt, cnt>0)
__global__ void __launch_bounds__(256) k_scan() {
    __shared__ int sbid;
    __shared__ unsigned long long sexcl;
    __shared__ int ssum[256], sflg[256];
    int t = threadIdx.x;
    if (t == 0) sbid = atomicAdd(&d_bidc, 1);
    __syncthreads();
    int bid = sbid;
    int base = bid * SCAN_CHUNK + t * 8;
    int v[8], f[8];
    int run1 = 0, run2 = 0;
#pragma unroll
    for (int j = 0; j < 8; j++) {
        int idx = base + j;
        int c = (idx < NSEG) ? d_cnt[idx] : 0;
        v[j] = run1; f[j] = run2;
        run1 += c; run2 += (c > 0);
    }
    ssum[t] = run1; sflg[t] = run2;
    __syncthreads();
    for (int d = 1; d < 256; d <<= 1) {
        int a = 0, b = 0;
        if (t >= d) { a = ssum[t - d]; b = sflg[t - d]; }
        __syncthreads();
        if (t >= d) { ssum[t] += a; sflg[t] += b; }
        __syncthreads();
    }
    unsigned long long blockAgg =
        ((unsigned long long)(unsigned)ssum[255] << 32) | (unsigned)sflg[255];
    if (t == 0) {
        *((volatile unsigned long long*)&d_agg[bid]) = blockAgg;
        __threadfence();
        *((volatile int*)&d_stat[bid]) = 1;
    }
    if (t < 32) {
        unsigned long long excl = 0;
        int p = bid - 1;
        while (p >= 0) {
            int pi = p - t;
            int st;
            do {
                st = (pi >= 0) ? *((volatile int*)&d_stat[pi]) : 2;
            } while (__any_sync(FULLM, st == 0));
            unsigned m2 = __ballot_sync(FULLM, pi >= 0 && st == 2);
            if (m2) {
                int lead = __ffs(m2) - 1;
                unsigned long long vv = 0ull;
                if (pi >= 0) {
                    if (t < lead)       vv = *((volatile unsigned long long*)&d_agg[pi]);
                    else if (t == lead) vv = *((volatile unsigned long long*)&d_incl[pi]);
                }
                for (int o = 16; o > 0; o >>= 1) vv += __shfl_down_sync(FULLM, vv, o);
                excl += __shfl_sync(FULLM, vv, 0);
                break;
            } else {
                unsigned long long vv =
                    (pi >= 0) ? *((volatile unsigned long long*)&d_agg[pi]) : 0ull;
                for (int o = 16; o > 0; o >>= 1) vv += __shfl_down_sync(FULLM, vv, o);
                excl += __shfl_sync(FULLM, vv, 0);
                p -= 32;
            }
        }
        if (t == 0) {
            sexcl = excl;
            *((volatile unsigned long long*)&d_incl[bid]) = excl + blockAgg;
            __threadfence();
            *((volatile int*)&d_stat[bid]) = 2;
        }
    }
    __syncthreads();
    int exS = (int)(sexcl >> 32), exF = (int)(sexcl & 0xffffffffu);
    int ts = exS + ssum[t] - run1;
    int tf = exF + sflg[t] - run2;
#pragma unroll
    for (int j = 0; j < 8; j++) {
        int idx = base + j;
        if (idx < NSEG) {
            int o = ts + v[j];
            d_off[idx] = o; d_cur[idx] = o; d_cpt[idx] = tf + f[j];
        }
    }
    if (bid == NB2 - 1 && t == 255) {
        d_off[NSEG] = exS + ssum[255];
        d_cpt[NSEG] = exF + sflg[255];
    }
}

// compact CSR + counting-sort scatter + state reset for next replay
__global__ void k_cscat(const int* __restrict__ et, const int* __restrict__ dst,
                        const int* __restrict__ src, int E) {
    int i = blockIdx.x * blockDim.x + threadIdx.x;
    if (i < NSEG) {
        int c = d_cnt[i];
        if (c > 0) {
            int cc = d_cpt[i];
            d_coff[cc] = d_off[i];
            d_cdst[cc] = i % N_NODES;
        }
        d_cnt[i] = 0;
    }
    if (i < E) {
        int key = et[i] * N_NODES + dst[i];
        int p = atomicAdd(&d_cur[key], 1);
        d_srcn[p] = src[i];
    }
    if (i < NB2) d_stat[i] = 0;
    if (i == 0) {
        d_bidc = 0;
        d_coff[d_cpt[NSEG]] = E;
    }
}

// ---------------- fused mean aggregation + tf32 MMA + red scatter ----------------
// Block = 128 compact segments of one relation.
// DOUT==64: 128 threads / 4 warps; each warp owns 32 rows = 2 MMA tiles, so each
//   B fragment (LDG.128) is reused for 2 tiles -> B L1 traffic per block halved
//   vs the 8-warp version, with UNCHANGED 35KB smem footprint (occupancy kept).
// DOUT==8:  256 threads, SIMT (proven R11 shape).
template <int DOUT>
__global__ void __launch_bounds__(DOUT == 64 ? 128 : 256)
k_agg(const float* __restrict__ x, const float* __restrict__ W) {
    constexpr int NTH = (DOUT == 64) ? 128 : 256;
    extern __shared__ float smem[];
    float* Ws;   // only for DOUT==8
    float* As;
    if (DOUT == 8) { Ws = smem; As = smem + 64 * 8; }
    else           { Ws = nullptr; As = smem; }
    int* sso = (int*)(As + 128 * 68);   // [129]
    int* sdn = sso + 129;               // [128]

    int r = blockIdx.y;
    int t = threadIdx.x, lane = t & 31, w = t >> 5;

    int baseC = d_cpt[r * N_NODES];
    int Cend  = d_cpt[(r + 1) * N_NODES];
    int cb    = baseC + blockIdx.x * 128;
    if (cb >= Cend) return;

    if (DOUT == 8) {
        const float* Wr = W + r * 64 * 8;
        for (int i = t; i < 64 * 8; i += NTH) Ws[i] = Wr[i];
    }
    // segment metadata
    for (int i = t; i < 129; i += NTH) sso[i] = d_coff[min(cb + i, Cend)];
    for (int i = t; i < 128; i += NTH) sdn[i] = (cb + i < Cend) ? d_cdst[cb + i] : -1;
    __syncthreads();

    // ---- gather: 8 threads/segment, chunks of 4 unrolled passes ----
    {
        constexpr int SPP = NTH / 8;            // segments per pass
        constexpr int NCH = 128 / (4 * SPP);    // chunks
        int sub  = t & 7;
        int c0   = sub * 8;
        int segl = t >> 3;
#pragma unroll
        for (int ch = 0; ch < NCH; ch++) {
            int sb = ch * 4 * SPP;
            int e0[4], e1[4], s0[4];
#pragma unroll
            for (int p = 0; p < 4; p++) {
                int sg = sb + p * SPP + segl;
                e0[p] = sso[sg];
                e1[p] = sso[sg + 1];
            }
#pragma unroll
            for (int p = 0; p < 4; p++)
                s0[p] = (e1[p] > e0[p]) ? __ldg(&d_srcn[e0[p]]) : -1;
            float4 A0[4], A1[4];
#pragma unroll
            for (int p = 0; p < 4; p++) {
                if (s0[p] >= 0) {
                    const float4* xp = (const float4*)(x + s0[p] * 64 + c0);
                    A0[p] = __ldg(xp);
                    A1[p] = __ldg(xp + 1);
                } else {
                    A0[p] = make_float4(0.f, 0.f, 0.f, 0.f);
                    A1[p] = make_float4(0.f, 0.f, 0.f, 0.f);
                }
            }
#pragma unroll
            for (int p = 0; p < 4; p++) {
                for (int e = e0[p] + 1; e < e1[p]; e++) {
                    int s2 = __ldg(&d_srcn[e]);
                    const float4* xq = (const float4*)(x + s2 * 64 + c0);
                    float4 v0 = __ldg(xq), v1 = __ldg(xq + 1);
                    A0[p].x += v0.x; A0[p].y += v0.y; A0[p].z += v0.z; A0[p].w += v0.w;
                    A1[p].x += v1.x; A1[p].y += v1.y; A1[p].z += v1.z; A1[p].w += v1.w;
                }
            }
#pragma unroll
            for (int p = 0; p < 4; p++) {
                int cnt = e1[p] - e0[p];
                float inv = (cnt > 0) ? 1.f / (float)cnt : 0.f;
                int sg = sb + p * SPP + segl;
                float* dp = As + sg * 68 + c0;
                float4 o0, o1;
                o0.x = tf32r(A0[p].x * inv); o0.y = tf32r(A0[p].y * inv);
                o0.z = tf32r(A0[p].z * inv); o0.w = tf32r(A0[p].w * inv);
                o1.x = tf32r(A1[p].x * inv); o1.y = tf32r(A1[p].y * inv);
                o1.z = tf32r(A1[p].z * inv); o1.w = tf32r(A1[p].w * inv);
                *(float4*)dp = o0;
                *(float4*)(dp + 4) = o1;
            }
        }
    }
    __syncthreads();

    if (DOUT == 64) {
        int g = lane >> 2, q = lane & 3;
        const float* AL0 = As + (w * 32 + g) * 68;    // tile 0: rows g, g+8
        const float* AL8 = AL0 + 8 * 68;
        const float* AH0 = AL0 + 16 * 68;             // tile 1: rows g+16, g+24
        const float* AH8 = AL0 + 24 * 68;
        const float4* Wf = (const float4*)(W + r * 4096);
        float mac[2][8][4];
#pragma unroll
        for (int tt = 0; tt < 2; tt++)
#pragma unroll
            for (int j = 0; j < 8; j++)
#pragma unroll
                for (int i = 0; i < 4; i++) mac[tt][j][i] = 0.f;
#pragma unroll
        for (int kk = 0; kk < 8; kk++) {
            int k0 = kk * 8;
            uint32_t L0 = __float_as_uint(AL0[k0 + q]);
            uint32_t L1 = __float_as_uint(AL8[k0 + q]);
            uint32_t L2 = __float_as_uint(AL0[k0 + q + 4]);
            uint32_t L3 = __float_as_uint(AL8[k0 + q + 4]);
            uint32_t H0 = __float_as_uint(AH0[k0 + q]);
            uint32_t H1 = __float_as_uint(AH8[k0 + q]);
            uint32_t H2 = __float_as_uint(AH0[k0 + q + 4]);
            uint32_t H3 = __float_as_uint(AH8[k0 + q + 4]);
#pragma unroll
            for (int jp = 0; jp < 4; jp++) {
                float4 bf = __ldg(&Wf[(kk * 4 + jp) * 32 + lane]);
                uint32_t B0 = __float_as_uint(bf.x);
                uint32_t B1 = __float_as_uint(bf.y);
                uint32_t B2 = __float_as_uint(bf.z);
                uint32_t B3 = __float_as_uint(bf.w);
                asm volatile(
                    "mma.sync.aligned.m16n8k8.row.col.f32.tf32.tf32.f32 "
                    "{%0,%1,%2,%3}, {%4,%5,%6,%7}, {%8,%9}, {%0,%1,%2,%3};"
                    : "+f"(mac[0][2*jp][0]), "+f"(mac[0][2*jp][1]),
                      "+f"(mac[0][2*jp][2]), "+f"(mac[0][2*jp][3])
                    : "r"(L0), "r"(L1), "r"(L2), "r"(L3), "r"(B0), "r"(B1));
                asm volatile(
                    "mma.sync.aligned.m16n8k8.row.col.f32.tf32.tf32.f32 "
                    "{%0,%1,%2,%3}, {%4,%5,%6,%7}, {%8,%9}, {%0,%1,%2,%3};"
                    : "+f"(mac[0][2*jp+1][0]), "+f"(mac[0][2*jp+1][1]),
                      "+f"(mac[0][2*jp+1][2]), "+f"(mac[0][2*jp+1][3])
                    : "r"(L0), "r"(L1), "r"(L2), "r"(L3), "r"(B2), "r"(B3));
                asm volatile(
                    "mma.sync.aligned.m16n8k8.row.col.f32.tf32.tf32.f32 "
                    "{%0,%1,%2,%3}, {%4,%5,%6,%7}, {%8,%9}, {%0,%1,%2,%3};"
                    : "+f"(mac[1][2*jp][0]), "+f"(mac[1][2*jp][1]),
                      "+f"(mac[1][2*jp][2]), "+f"(mac[1][2*jp][3])
                    : "r"(H0), "r"(H1), "r"(H2), "r"(H3), "r"(B0), "r"(B1));
                asm volatile(
                    "mma.sync.aligned.m16n8k8.row.col.f32.tf32.tf32.f32 "
                    "{%0,%1,%2,%3}, {%4,%5,%6,%7}, {%8,%9}, {%0,%1,%2,%3};"
                    : "+f"(mac[1][2*jp+1][0]), "+f"(mac[1][2*jp+1][1]),
                      "+f"(mac[1][2*jp+1][2]), "+f"(mac[1][2*jp+1][3])
                    : "r"(H0), "r"(H1), "r"(H2), "r"(H3), "r"(B2), "r"(B3));
            }
        }
#pragma unroll
        for (int tt = 0; tt < 2; tt++) {
            int dA = sdn[w * 32 + tt * 16 + g];
            int dB = sdn[w * 32 + tt * 16 + 8 + g];
#pragma unroll
            for (int j = 0; j < 8; j++) {
                int col = j * 8 + 2 * q;
                if (dA >= 0) red2(&d_msg[dA * 64 + col], mac[tt][j][0], mac[tt][j][1]);
                if (dB >= 0) red2(&d_msg[dB * 64 + col], mac[tt][j][2], mac[tt][j][3]);
            }
        }
    } else {
        int row = t >> 1;
        int c0 = (t & 1) * 4;
        const float* Ar = As + row * 68;
        float s0 = 0.f, s1 = 0.f, s2 = 0.f, s3 = 0.f;
#pragma unroll
        for (int k = 0; k < 64; k++) {
            float a = Ar[k];
            float4 b = *(const float4*)&Ws[k * 8 + c0];
            s0 += a * b.x; s1 += a * b.y; s2 += a * b.z; s3 += a * b.w;
        }
        int dn = sdn[row];
        if (dn >= 0) red4(&d_msg[dn * 8 + c0], s0, s1, s2, s3);
    }
}

// epilogue: h = relu(msg + x@root + bias); re-zero msg
__global__ void k_rootrelu(const float* __restrict__ x, const float* __restrict__ root,
                           const float* __restrict__ bias, float* __restrict__ h) {
    int idx = blockIdx.x * blockDim.x + threadIdx.x;
    if (idx >= N_NODES * 64) return;
    int n = idx >> 6, o = idx & 63;
    float acc = bias[o] + d_msg[idx];
    d_msg[idx] = 0.f;
    const float* xr = x + n * 64;
#pragma unroll 16
    for (int i = 0; i < 64; i++) acc += xr[i] * root[i * 64 + o];
    h[idx] = acc > 0.f ? acc : 0.f;
}

// final epilogue: out = log_softmax(msg + x@root + bias); re-zero msg slice
__global__ void k_rootlsm(const float* __restrict__ x, const float* __restrict__ root,
                          const float* __restrict__ bias, float* __restrict__ out) {
    int n = blockIdx.x * blockDim.x + threadIdx.x;
    if (n >= N_NODES) return;
    float v[8];
#pragma unroll
    for (int c = 0; c < 8; c++) {
        v[c] = bias[c] + d_msg[n * 8 + c];
        d_msg[n * 8 + c] = 0.f;
    }
    const float* xr = x + n * 64;
    for (int i = 0; i < 64; i++) {
        float xv = xr[i];
#pragma unroll
        for (int c = 0; c < 8; c++) v[c] += xv * root[i * 8 + c];
    }
    float m = -1e30f;
#pragma unroll
    for (int c = 0; c < 8; c++) m = fmaxf(m, v[c]);
    float s = 0.f;
#pragma unroll
    for (int c = 0; c < 8; c++) s += expf(v[c] - m);
    float ls = logf(s) + m;
#pragma unroll
    for (int c = 0; c < 8; c++) out[n * 8 + c] = v[c] - ls;
}

// ---------------- launch ----------------
extern "C" void kernel_launch(void* const* d_in, const int* in_sizes, int n_in,
                              void* d_out, int out_size) {
    const float* x0 = (const float*)d_in[0];
    const int* ei = (const int*)d_in[1];
    const int* et = (const int*)d_in[2];
    int E = in_sizes[2];
    const int* src = ei;
    const int* dst = ei + E;

    void *pA, *pB, *pW0, *pW1, *pW2;
    cudaGetSymbolAddress(&pA, d_hA);
    cudaGetSymbolAddress(&pB, d_hB);
    cudaGetSymbolAddress(&pW0, d_W0);
    cudaGetSymbolAddress(&pW1, d_W1);
    cudaGetSymbolAddress(&pW2, d_W2);
    float* hA = (float*)pA;
    float* hB = (float*)pB;

    const int SMEM64 = (128 * 68) * 4 + 129 * 4 + 128 * 4;
    const int SMEM8  = (64 * 8 + 128 * 68) * 4 + 129 * 4 + 128 * 4;
    cudaFuncSetAttribute(k_agg<64>, cudaFuncAttributeMaxDynamicSharedMemorySize, SMEM64);
    cudaFuncSetAttribute(k_agg<8>,  cudaFuncAttributeMaxDynamicSharedMemorySize, SMEM8);

    const int NZ = N_NODES * 64;
    dim3 grid((N_NODES + 127) / 128, N_REL);

    // 1: prep;  2: scan;  3: compact+scatter+reset;  4: k_agg<64>  <- ncu slot
    k_prep<<<(E + 255) / 256, 256>>>(et, dst, E,
        (const float*)d_in[3], (const float*)d_in[4],
        (const float*)d_in[7], (const float*)d_in[8],
        (const float*)d_in[11], (const float*)d_in[12]);
    k_scan<<<NB2, 256>>>();
    k_cscat<<<(NSEG + 255) / 256, 256>>>(et, dst, src, E);

    k_agg<64><<<grid, 128, SMEM64>>>(x0, (const float*)pW0);
    k_rootrelu<<<(NZ + 255) / 256, 256>>>(x0, (const float*)d_in[5], (const float*)d_in[6], hA);

    k_agg<64><<<grid, 128, SMEM64>>>(hA, (const float*)pW1);
    k_rootrelu<<<(NZ + 255) / 256, 256>>>(hA, (const float*)d_in[9], (const float*)d_in[10], hB);

    k_agg<8><<<grid, 256, SMEM8>>>(hB, (const float*)pW2);
    k_rootlsm<<<(N_NODES + 255) / 256, 256>>>(hB, (const float*)d_in[13], (const float*)d_in[14],
                                              (float*)d_out);
}